// round 2
// baseline (speedup 1.0000x reference)
#include <cuda_runtime.h>

#define BB 4
#define LQ 512
#define LK 512
#define HH 256

#define CTX_ELEMS (BB*LQ*HH)
#define LOG2E2 2.885390081777927f   // 2*log2(e)

static __device__ float g_q[BB*LQ*HH];  // Eq = exp(2*q_proj)
static __device__ float g_k[BB*LK*HH];  // Ek = exp(2*k_proj)
static __device__ float g_s[BB*LQ*LK];  // raw scores s = sum_h We*r  (score = -2s + const)

__device__ __forceinline__ float ex2a(float x) {
    float e;
    asm("ex2.approx.ftz.f32 %0, %1;" : "=f"(e) : "f"(x));
    return e;
}
__device__ __forceinline__ float rcpa(float x) {
    float r;
    asm("rcp.approx.ftz.f32 %0, %1;" : "=f"(r) : "f"(x));
    return r;
}

// ---------------------------------------------------------------------------
// K1: projections + exp epilogue. out[m,o] = exp(2*(sum_h in[m,h]*W[o,h] + b[o]))
// blockIdx.z: 0 -> (query,Wq,bq) -> g_q ; 1 -> (values,Wk,bk) -> g_k
// Tile 64x64, BK=32, 256 threads, 4x4 register tile.
// ---------------------------------------------------------------------------
__global__ __launch_bounds__(256) void proj_kernel(
    const float* __restrict__ query, const float* __restrict__ values,
    const float* __restrict__ Wq, const float* __restrict__ bq,
    const float* __restrict__ Wk, const float* __restrict__ bk)
{
    const float* in   = blockIdx.z ? values : query;
    const float* W    = blockIdx.z ? Wk : Wq;
    const float* bias = blockIdx.z ? bk : bq;
    float* out        = blockIdx.z ? g_k : g_q;

    __shared__ float As[32][68];  // [k][m] transposed, padded
    __shared__ float Bs[32][68];  // [k][n] transposed, padded

    int tid = threadIdx.x;
    int tx = tid & 15, ty = tid >> 4;
    int m0 = blockIdx.x * 64, n0 = blockIdx.y * 64;

    float acc[4][4] = {};

    for (int k0 = 0; k0 < HH; k0 += 32) {
        #pragma unroll
        for (int r = 0; r < 2; r++) {
            int idx = tid + r * 256;     // 512 float4 slots
            int row = idx >> 3;          // 0..63
            int c4  = idx & 7;           // 0..7
            float4 va = *(const float4*)&in[(size_t)(m0 + row) * HH + k0 + c4 * 4];
            As[c4*4+0][row] = va.x; As[c4*4+1][row] = va.y;
            As[c4*4+2][row] = va.z; As[c4*4+3][row] = va.w;
            float4 vb = *(const float4*)&W[(size_t)(n0 + row) * HH + k0 + c4 * 4];
            Bs[c4*4+0][row] = vb.x; Bs[c4*4+1][row] = vb.y;
            Bs[c4*4+2][row] = vb.z; Bs[c4*4+3][row] = vb.w;
        }
        __syncthreads();
        #pragma unroll 8
        for (int kk = 0; kk < 32; kk++) {
            float4 a = *(const float4*)&As[kk][ty * 4];
            float4 b = *(const float4*)&Bs[kk][tx * 4];
            float av[4] = {a.x, a.y, a.z, a.w};
            float bv[4] = {b.x, b.y, b.z, b.w};
            #pragma unroll
            for (int i = 0; i < 4; i++)
                #pragma unroll
                for (int j = 0; j < 4; j++)
                    acc[i][j] = fmaf(av[i], bv[j], acc[i][j]);
        }
        __syncthreads();
    }

    #pragma unroll
    for (int i = 0; i < 4; i++) {
        #pragma unroll
        for (int j = 0; j < 4; j++) {
            int m = m0 + ty * 4 + i;
            int n = n0 + tx * 4 + j;
            out[(size_t)m * HH + n] = ex2a((acc[i][j] + bias[n]) * LOG2E2);
        }
    }
}

// ---------------------------------------------------------------------------
// K2: scores. s[q,k] = sum_h We[h] / (Eq[q,h]*Ek[k,h] + 1)
// (reference score = C - 2*s + be; additive consts drop in softmax)
// Block: 256 threads = 8 warps. Warp lane = (k_local*8 + c):
//   k_local in [0,4): k column, c in [0,8): h-chunk of 32.
// Block tile: 16 q x 32 k x full H. Ek+We chunks in registers, reused over q.
// Eq loads are warp-broadcast (8 distinct addrs/instr), L1-hot.
// ---------------------------------------------------------------------------
#define SK_QT 16

__global__ __launch_bounds__(256) void score_kernel(const float* __restrict__ We)
{
    int b  = blockIdx.z;
    int q0 = blockIdx.x * SK_QT;
    int k0 = blockIdx.y * 32;
    int lane = threadIdx.x & 31;
    int warp = threadIdx.x >> 5;
    int kl = lane >> 3;           // 0..3
    int c  = lane & 7;            // 0..7
    int k  = k0 + warp * 4 + kl;
    int h0 = c * 32;

    float we[32], ek[32];
    const float* wep = We + h0;
    const float* ekp = g_k + ((size_t)(b * LK + k)) * HH + h0;
    #pragma unroll
    for (int i = 0; i < 8; i++) {
        float4 w4 = *(const float4*)&wep[i * 4];
        we[i*4+0] = w4.x; we[i*4+1] = w4.y; we[i*4+2] = w4.z; we[i*4+3] = w4.w;
        float4 e4 = *(const float4*)&ekp[i * 4];
        ek[i*4+0] = e4.x; ek[i*4+1] = e4.y; ek[i*4+2] = e4.z; ek[i*4+3] = e4.w;
    }

    const float* eqbase = g_q + ((size_t)(b * LQ + q0)) * HH + h0;
    float* srow = g_s + ((size_t)(b * LQ + q0)) * LK + k;

    #pragma unroll 4
    for (int q = 0; q < SK_QT; q++) {
        float acc = 0.0f;
        const float* eqp = eqbase + (size_t)q * HH;
        #pragma unroll
        for (int i = 0; i < 8; i++) {
            float4 e = *(const float4*)&eqp[i * 4];
            float t0 = fmaf(e.x, ek[i*4+0], 1.0f);
            float t1 = fmaf(e.y, ek[i*4+1], 1.0f);
            float t2 = fmaf(e.z, ek[i*4+2], 1.0f);
            float t3 = fmaf(e.w, ek[i*4+3], 1.0f);
            acc = fmaf(we[i*4+0], rcpa(t0), acc);
            acc = fmaf(we[i*4+1], rcpa(t1), acc);
            acc = fmaf(we[i*4+2], rcpa(t2), acc);
            acc = fmaf(we[i*4+3], rcpa(t3), acc);
        }
        acc += __shfl_xor_sync(0xffffffffu, acc, 1);
        acc += __shfl_xor_sync(0xffffffffu, acc, 2);
        acc += __shfl_xor_sync(0xffffffffu, acc, 4);
        if (c == 0) srow[(size_t)q * LK] = acc;
    }
}

// ---------------------------------------------------------------------------
// K2b: softmax over k of score = -2*s. Warp per row (512 values, 16/lane).
// ---------------------------------------------------------------------------
__global__ __launch_bounds__(256) void softmax_kernel(float* __restrict__ attn)
{
    int row  = blockIdx.x * 8 + (threadIdx.x >> 5);   // 0 .. B*LQ-1
    int lane = threadIdx.x & 31;
    const float* s = g_s + (size_t)row * LK;

    float vals[16];
    float m = -1e30f;
    #pragma unroll
    for (int i = 0; i < 16; i++) {
        vals[i] = -2.0f * s[lane + 32 * i];
        m = fmaxf(m, vals[i]);
    }
    #pragma unroll
    for (int o = 16; o; o >>= 1) m = fmaxf(m, __shfl_xor_sync(0xffffffffu, m, o));
    float sum = 0.0f;
    #pragma unroll
    for (int i = 0; i < 16; i++) {
        vals[i] = ex2a((vals[i] - m) * 1.4426950408889634f);
        sum += vals[i];
    }
    #pragma unroll
    for (int o = 16; o; o >>= 1) sum += __shfl_xor_sync(0xffffffffu, sum, o);
    float inv = 1.0f / sum;

    float* arow = attn + (size_t)row * LK;
    #pragma unroll
    for (int i = 0; i < 16; i++)
        arow[lane + 32 * i] = vals[i] * inv;
}

// ---------------------------------------------------------------------------
// K3: context = attn @ values (batched NN GEMM, M=512, N=256, K=512).
// Tile 32(M) x 64(N), BK=32, 256 threads, 2x4 register tile.
// ---------------------------------------------------------------------------
__global__ __launch_bounds__(256) void context_kernel(
    const float* __restrict__ values, const float* __restrict__ attn,
    float* __restrict__ ctx)
{
    __shared__ float As[32][36];   // [k][m], m=32, padded
    __shared__ float Vs[32][68];   // [k][n], n=64, padded

    int tid = threadIdx.x;
    int b = blockIdx.z;
    int q0 = blockIdx.x * 32;
    int n0 = blockIdx.y * 64;
    int tx = tid & 15, ty = tid >> 4;

    const float* Abase = attn + (size_t)b * LQ * LK;
    const float* Vbase = values + (size_t)b * LK * HH;

    float acc[2][4] = {};

    for (int k0 = 0; k0 < LK; k0 += 32) {
        {
            int m = tid >> 3, c4 = tid & 7;
            float4 va = *(const float4*)&Abase[(size_t)(q0 + m) * LK + k0 + c4 * 4];
            As[c4*4+0][m] = va.x; As[c4*4+1][m] = va.y;
            As[c4*4+2][m] = va.z; As[c4*4+3][m] = va.w;
        }
        #pragma unroll
        for (int r = 0; r < 2; r++) {
            int idx = tid + r * 256;
            int kk = idx >> 4, c4 = idx & 15;
            *(float4*)&Vs[kk][c4 * 4] =
                *(const float4*)&Vbase[(size_t)(k0 + kk) * HH + n0 + c4 * 4];
        }
        __syncthreads();
        #pragma unroll 8
        for (int kk = 0; kk < 32; kk++) {
            float2 a = *(const float2*)&As[kk][ty * 2];
            float4 v = *(const float4*)&Vs[kk][tx * 4];
            acc[0][0] = fmaf(a.x, v.x, acc[0][0]);
            acc[0][1] = fmaf(a.x, v.y, acc[0][1]);
            acc[0][2] = fmaf(a.x, v.z, acc[0][2]);
            acc[0][3] = fmaf(a.x, v.w, acc[0][3]);
            acc[1][0] = fmaf(a.y, v.x, acc[1][0]);
            acc[1][1] = fmaf(a.y, v.y, acc[1][1]);
            acc[1][2] = fmaf(a.y, v.z, acc[1][2]);
            acc[1][3] = fmaf(a.y, v.w, acc[1][3]);
        }
        __syncthreads();
    }

    #pragma unroll
    for (int i = 0; i < 2; i++) {
        #pragma unroll
        for (int j = 0; j < 4; j++) {
            ctx[(size_t)(b * LQ + q0 + ty * 2 + i) * HH + n0 + tx * 4 + j] = acc[i][j];
        }
    }
}

// ---------------------------------------------------------------------------
// Launch: proj(+exp) -> scores -> softmax -> context.
// Output layout: [context (B*LQ*H) | attention (B*LQ*LK)]. be unused.
// ---------------------------------------------------------------------------
extern "C" void kernel_launch(void* const* d_in, const int* in_sizes, int n_in,
                              void* d_out, int out_size)
{
    const float* query  = (const float*)d_in[0];
    const float* values = (const float*)d_in[1];
    const float* Wq     = (const float*)d_in[2];
    const float* bq     = (const float*)d_in[3];
    const float* Wk     = (const float*)d_in[4];
    const float* bk     = (const float*)d_in[5];
    const float* We     = (const float*)d_in[6];
    // d_in[7] = be, softmax-invariant

    float* out  = (float*)d_out;
    float* ctx  = out;
    float* attn = out + CTX_ELEMS;

    proj_kernel<<<dim3(32, 4, 2), 256>>>(query, values, Wq, bq, Wk, bk);
    score_kernel<<<dim3(LQ / SK_QT, LK / 32, BB), 256>>>(We);
    softmax_kernel<<<dim3(BB * LQ / 8), 256>>>(attn);
    context_kernel<<<dim3(16, 4, 4), 256>>>(values, attn, ctx);
}

// round 3
// speedup vs baseline: 2.7420x; 2.7420x over previous
#include <cuda_runtime.h>

#define BB 4
#define LQ 512
#define LK 512
#define HH 256

#define CTX_ELEMS (BB*LQ*HH)
#define LOG2E2 2.885390081777927f   // 2*log2(e)

static __device__ float g_q[BB*LQ*HH];  // Eq = exp(2*q_proj)
static __device__ float g_k[BB*LK*HH];  // Ek = exp(2*k_proj)
static __device__ float g_s[BB*LQ*LK];  // raw scores s ; ref score = C - 2s (consts drop)

__device__ __forceinline__ float ex2a(float x) {
    float e;
    asm("ex2.approx.ftz.f32 %0, %1;" : "=f"(e) : "f"(x));
    return e;
}
__device__ __forceinline__ float rcpa(float x) {
    float r;
    asm("rcp.approx.ftz.f32 %0, %1;" : "=f"(r) : "f"(x));
    return r;
}

// ---------------------------------------------------------------------------
// K1: projections + exp epilogue. out[m,o] = exp(2*(sum_h in[m,h]*W[o,h]+b[o]))
// Tile 64x64, BK=32, 256 threads, 4x4 register tile.
// ---------------------------------------------------------------------------
__global__ __launch_bounds__(256) void proj_kernel(
    const float* __restrict__ query, const float* __restrict__ values,
    const float* __restrict__ Wq, const float* __restrict__ bq,
    const float* __restrict__ Wk, const float* __restrict__ bk)
{
    const float* in   = blockIdx.z ? values : query;
    const float* W    = blockIdx.z ? Wk : Wq;
    const float* bias = blockIdx.z ? bk : bq;
    float* out        = blockIdx.z ? g_k : g_q;

    __shared__ float As[32][68];
    __shared__ float Bs[32][68];

    int tid = threadIdx.x;
    int tx = tid & 15, ty = tid >> 4;
    int m0 = blockIdx.x * 64, n0 = blockIdx.y * 64;

    float acc[4][4] = {};

    for (int k0 = 0; k0 < HH; k0 += 32) {
        #pragma unroll
        for (int r = 0; r < 2; r++) {
            int idx = tid + r * 256;
            int row = idx >> 3;
            int c4  = idx & 7;
            float4 va = *(const float4*)&in[(size_t)(m0 + row) * HH + k0 + c4 * 4];
            As[c4*4+0][row] = va.x; As[c4*4+1][row] = va.y;
            As[c4*4+2][row] = va.z; As[c4*4+3][row] = va.w;
            float4 vb = *(const float4*)&W[(size_t)(n0 + row) * HH + k0 + c4 * 4];
            Bs[c4*4+0][row] = vb.x; Bs[c4*4+1][row] = vb.y;
            Bs[c4*4+2][row] = vb.z; Bs[c4*4+3][row] = vb.w;
        }
        __syncthreads();
        #pragma unroll 8
        for (int kk = 0; kk < 32; kk++) {
            float4 a = *(const float4*)&As[kk][ty * 4];
            float4 b = *(const float4*)&Bs[kk][tx * 4];
            float av[4] = {a.x, a.y, a.z, a.w};
            float bv[4] = {b.x, b.y, b.z, b.w};
            #pragma unroll
            for (int i = 0; i < 4; i++)
                #pragma unroll
                for (int j = 0; j < 4; j++)
                    acc[i][j] = fmaf(av[i], bv[j], acc[i][j]);
        }
        __syncthreads();
    }

    #pragma unroll
    for (int i = 0; i < 4; i++)
        #pragma unroll
        for (int j = 0; j < 4; j++) {
            int m = m0 + ty * 4 + i;
            int n = n0 + tx * 4 + j;
            out[(size_t)m * HH + n] = ex2a((acc[i][j] + bias[n]) * LOG2E2);
        }
}

// ---------------------------------------------------------------------------
// K2: scores. s[q,k] = sum_h We[h] / (Eq[q,h]*Ek[k,h] + 1), pair-rcp trick:
//   we0/t0 + we1/t1 = (we0*t1 + we1*t0) * rcp(t0*t1),  t = fma(eq,ek,1)>=1.
// Thread = (q in [0,32), hc in [0,8)); eq[32]+we[32] persistent registers,
// ek streamed from padded smem (LDS.64, conflict-free broadcast).
// Block tile: 32 q x 128 k (4 staged sub-tiles of 32 k).
// ---------------------------------------------------------------------------
#define SQ 32
#define SKT 32
#define KCH 128
#define EK_PITCH 272   // 8*34 floats; hc*34 keeps float2 alignment + distinct banks

__global__ __launch_bounds__(256) void score_kernel(const float* __restrict__ We)
{
    __shared__ float eks[SKT][EK_PITCH];

    int b   = blockIdx.z;
    int q0  = blockIdx.x * SQ;
    int k0  = blockIdx.y * KCH;
    int tid = threadIdx.x;
    int q   = tid >> 3;      // 0..31 (also staging k-row)
    int hc  = tid & 7;       // 0..7  h-chunk of 32

    // persistent registers: eq chunk + we chunk (loaded once)
    float eq[32], we[32];
    {
        const float* eqp = g_q + ((size_t)(b * LQ + q0 + q)) * HH + hc * 32;
        const float* wep = We + hc * 32;
        #pragma unroll
        for (int i = 0; i < 8; i++) {
            float4 e4 = *(const float4*)&eqp[i * 4];
            eq[i*4+0] = e4.x; eq[i*4+1] = e4.y; eq[i*4+2] = e4.z; eq[i*4+3] = e4.w;
            float4 w4 = *(const float4*)&wep[i * 4];
            we[i*4+0] = w4.x; we[i*4+1] = w4.y; we[i*4+2] = w4.z; we[i*4+3] = w4.w;
        }
    }

    float* srow = g_s + ((size_t)(b * LQ + q0 + q)) * LK + k0;
    int lane = tid & 31;
    int hbase = hc * 34;

    for (int t = 0; t < KCH / SKT; t++) {
        __syncthreads();   // protect eks from previous sub-tile readers
        // stage: thread loads k-row 'q', its h-chunk, into padded layout
        {
            const float* ekp = g_k + ((size_t)(b * LK + k0 + t * SKT + q)) * HH + hc * 32;
            #pragma unroll
            for (int i = 0; i < 8; i++) {
                float4 e4 = *(const float4*)&ekp[i * 4];
                *(float2*)&eks[q][hbase + i*4]     = make_float2(e4.x, e4.y);
                *(float2*)&eks[q][hbase + i*4 + 2] = make_float2(e4.z, e4.w);
            }
        }
        __syncthreads();

        #pragma unroll 2
        for (int k = 0; k < SKT; k++) {
            float acc0 = 0.0f, acc1 = 0.0f;
            const float* ekr = &eks[k][hbase];
            #pragma unroll
            for (int p = 0; p < 16; p++) {
                float2 e2 = *(const float2*)&ekr[2 * p];
                float t0 = fmaf(eq[2*p],   e2.x, 1.0f);
                float t1 = fmaf(eq[2*p+1], e2.y, 1.0f);
                float den = t0 * t1;
                float num = fmaf(we[2*p], t1, we[2*p+1] * t0);
                if (p & 1) acc1 = fmaf(num, rcpa(den), acc1);
                else       acc0 = fmaf(num, rcpa(den), acc0);
            }
            float acc = acc0 + acc1;
            acc += __shfl_xor_sync(0xffffffffu, acc, 1);
            acc += __shfl_xor_sync(0xffffffffu, acc, 2);
            acc += __shfl_xor_sync(0xffffffffu, acc, 4);
            if ((lane & 7) == 0) srow[t * SKT + k] = acc;
        }
    }
}

// ---------------------------------------------------------------------------
// K2b: softmax over k of score = -2*s. Warp per row.
// ---------------------------------------------------------------------------
__global__ __launch_bounds__(256) void softmax_kernel(float* __restrict__ attn)
{
    int row  = blockIdx.x * 8 + (threadIdx.x >> 5);
    int lane = threadIdx.x & 31;
    const float* s = g_s + (size_t)row * LK;

    float vals[16];
    float m = -1e30f;
    #pragma unroll
    for (int i = 0; i < 16; i++) {
        vals[i] = -2.0f * s[lane + 32 * i];
        m = fmaxf(m, vals[i]);
    }
    #pragma unroll
    for (int o = 16; o; o >>= 1) m = fmaxf(m, __shfl_xor_sync(0xffffffffu, m, o));
    float sum = 0.0f;
    #pragma unroll
    for (int i = 0; i < 16; i++) {
        vals[i] = ex2a((vals[i] - m) * 1.4426950408889634f);
        sum += vals[i];
    }
    #pragma unroll
    for (int o = 16; o; o >>= 1) sum += __shfl_xor_sync(0xffffffffu, sum, o);
    float inv = 1.0f / sum;

    float* arow = attn + (size_t)row * LK;
    #pragma unroll
    for (int i = 0; i < 16; i++)
        arow[lane + 32 * i] = vals[i] * inv;
}

// ---------------------------------------------------------------------------
// K3: context = attn @ values (batched NN GEMM, M=512, N=256, K=512).
// Tile 64x64, BK=32, 256 threads, 4x4 register tile (proj-style).
// ---------------------------------------------------------------------------
__global__ __launch_bounds__(256) void context_kernel(
    const float* __restrict__ values, const float* __restrict__ attn,
    float* __restrict__ ctx)
{
    __shared__ float As[32][68];   // [k][m] transposed
    __shared__ float Vs[32][68];   // [k][n] direct

    int tid = threadIdx.x;
    int b  = blockIdx.z;
    int q0 = blockIdx.x * 64;
    int n0 = blockIdx.y * 64;
    int tx = tid & 15, ty = tid >> 4;

    const float* Abase = attn + (size_t)b * LQ * LK;
    const float* Vbase = values + (size_t)b * LK * HH;

    float acc[4][4] = {};

    for (int k0 = 0; k0 < LK; k0 += 32) {
        #pragma unroll
        for (int r = 0; r < 2; r++) {
            int idx = tid + r * 256;
            int row = idx >> 3;          // 0..63 (m)
            int c4  = idx & 7;           // 0..7
            float4 va = *(const float4*)&Abase[(size_t)(q0 + row) * LK + k0 + c4 * 4];
            As[c4*4+0][row] = va.x; As[c4*4+1][row] = va.y;
            As[c4*4+2][row] = va.z; As[c4*4+3][row] = va.w;
        }
        #pragma unroll
        for (int r = 0; r < 2; r++) {
            int idx = tid + r * 256;
            int kk = idx >> 4, c4 = idx & 15;   // 32 k rows x 16 float4
            *(float4*)&Vs[kk][c4 * 4] =
                *(const float4*)&Vbase[(size_t)(k0 + kk) * HH + n0 + c4 * 4];
        }
        __syncthreads();
        #pragma unroll 8
        for (int kk = 0; kk < 32; kk++) {
            float4 a = *(const float4*)&As[kk][ty * 4];
            float4 v = *(const float4*)&Vs[kk][tx * 4];
            float av[4] = {a.x, a.y, a.z, a.w};
            float vv[4] = {v.x, v.y, v.z, v.w};
            #pragma unroll
            for (int i = 0; i < 4; i++)
                #pragma unroll
                for (int j = 0; j < 4; j++)
                    acc[i][j] = fmaf(av[i], vv[j], acc[i][j]);
        }
        __syncthreads();
    }

    #pragma unroll
    for (int i = 0; i < 4; i++)
        #pragma unroll
        for (int j = 0; j < 4; j++)
            ctx[(size_t)(b * LQ + q0 + ty * 4 + i) * HH + n0 + tx * 4 + j] = acc[i][j];
}

// ---------------------------------------------------------------------------
// Launch: proj(+exp) -> scores -> softmax -> context.
// Output layout: [context (B*LQ*H) | attention (B*LQ*LK)]. be unused.
// ---------------------------------------------------------------------------
extern "C" void kernel_launch(void* const* d_in, const int* in_sizes, int n_in,
                              void* d_out, int out_size)
{
    const float* query  = (const float*)d_in[0];
    const float* values = (const float*)d_in[1];
    const float* Wq     = (const float*)d_in[2];
    const float* bq     = (const float*)d_in[3];
    const float* Wk     = (const float*)d_in[4];
    const float* bk     = (const float*)d_in[5];
    const float* We     = (const float*)d_in[6];
    // d_in[7] = be, softmax-invariant

    float* out  = (float*)d_out;
    float* ctx  = out;
    float* attn = out + CTX_ELEMS;

    proj_kernel<<<dim3(32, 4, 2), 256>>>(query, values, Wq, bq, Wk, bk);
    score_kernel<<<dim3(BB * LQ / SQ / BB, LK / KCH, BB), 256>>>(We);
    softmax_kernel<<<dim3(BB * LQ / 8), 256>>>(attn);
    context_kernel<<<dim3(LQ / 64, HH / 64, BB), 256>>>(values, attn, ctx);
}

// round 4
// speedup vs baseline: 2.8292x; 1.0318x over previous
#include <cuda_runtime.h>

#define BB 4
#define LQ 512
#define LK 512
#define HH 256

#define CTX_ELEMS (BB*LQ*HH)
#define LOG2E2 2.885390081777927f   // 2*log2(e)

static __device__ float g_q[BB*LQ*HH];      // Eq = exp(2*q_proj)
static __device__ float g_k[BB*LK*HH];      // Ek = exp(2*k_proj)
static __device__ float g_s[BB*LQ*LK];      // raw scores; ref score = C - 2s (consts drop)
static __device__ float g_part[2*CTX_ELEMS];// context split-K partials

__device__ __forceinline__ float ex2a(float x) {
    float e;
    asm("ex2.approx.ftz.f32 %0, %1;" : "=f"(e) : "f"(x));
    return e;
}
__device__ __forceinline__ float rcpa(float x) {
    float r;
    asm("rcp.approx.ftz.f32 %0, %1;" : "=f"(r) : "f"(x));
    return r;
}

// ---------------------------------------------------------------------------
// K1: projections + exp epilogue. out[m,o] = exp(2*(sum_h in[m,h]*W[o,h]+b[o]))
// Tile 64x64, BK=32, 256 threads, 4x4 reg tile. Double-buffered smem +
// register prefetch: LDG for tile t+1 issued before compute(t), STS after.
// ---------------------------------------------------------------------------
__global__ __launch_bounds__(256) void proj_kernel(
    const float* __restrict__ query, const float* __restrict__ values,
    const float* __restrict__ Wq, const float* __restrict__ bq,
    const float* __restrict__ Wk, const float* __restrict__ bk)
{
    const float* in   = blockIdx.z ? values : query;
    const float* W    = blockIdx.z ? Wk : Wq;
    const float* bias = blockIdx.z ? bk : bq;
    float* out        = blockIdx.z ? g_k : g_q;

    __shared__ float As[2][32][68];
    __shared__ float Bs[2][32][68];

    int tid = threadIdx.x;
    int tx = tid & 15, ty = tid >> 4;
    int m0 = blockIdx.x * 64, n0 = blockIdx.y * 64;

    int row0 = tid >> 3,       c40 = tid & 7;         // r=0 slot
    int row1 = (tid + 256) >> 3, c41 = (tid + 256) & 7; // r=1 slot

    float4 ra0, ra1, rb0, rb1;
    // preload k0 = 0
    ra0 = *(const float4*)&in[(size_t)(m0 + row0) * HH + c40 * 4];
    rb0 = *(const float4*)&W [(size_t)(n0 + row0) * HH + c40 * 4];
    ra1 = *(const float4*)&in[(size_t)(m0 + row1) * HH + c41 * 4];
    rb1 = *(const float4*)&W [(size_t)(n0 + row1) * HH + c41 * 4];

    // store tile 0 into buf 0
    As[0][c40*4+0][row0] = ra0.x; As[0][c40*4+1][row0] = ra0.y;
    As[0][c40*4+2][row0] = ra0.z; As[0][c40*4+3][row0] = ra0.w;
    Bs[0][c40*4+0][row0] = rb0.x; Bs[0][c40*4+1][row0] = rb0.y;
    Bs[0][c40*4+2][row0] = rb0.z; Bs[0][c40*4+3][row0] = rb0.w;
    As[0][c41*4+0][row1] = ra1.x; As[0][c41*4+1][row1] = ra1.y;
    As[0][c41*4+2][row1] = ra1.z; As[0][c41*4+3][row1] = ra1.w;
    Bs[0][c41*4+0][row1] = rb1.x; Bs[0][c41*4+1][row1] = rb1.y;
    Bs[0][c41*4+2][row1] = rb1.z; Bs[0][c41*4+3][row1] = rb1.w;
    __syncthreads();

    float acc[4][4] = {};
    int buf = 0;

    #pragma unroll 1
    for (int it = 0; it < HH / 32; it++) {
        int k1 = (it + 1) * 32;
        bool more = (it + 1 < HH / 32);
        if (more) {   // prefetch next tile into registers (latency overlapped)
            ra0 = *(const float4*)&in[(size_t)(m0 + row0) * HH + k1 + c40 * 4];
            rb0 = *(const float4*)&W [(size_t)(n0 + row0) * HH + k1 + c40 * 4];
            ra1 = *(const float4*)&in[(size_t)(m0 + row1) * HH + k1 + c41 * 4];
            rb1 = *(const float4*)&W [(size_t)(n0 + row1) * HH + k1 + c41 * 4];
        }
        #pragma unroll 8
        for (int kk = 0; kk < 32; kk++) {
            float4 a = *(const float4*)&As[buf][kk][ty * 4];
            float4 b = *(const float4*)&Bs[buf][kk][tx * 4];
            float av[4] = {a.x, a.y, a.z, a.w};
            float bv[4] = {b.x, b.y, b.z, b.w};
            #pragma unroll
            for (int i = 0; i < 4; i++)
                #pragma unroll
                for (int j = 0; j < 4; j++)
                    acc[i][j] = fmaf(av[i], bv[j], acc[i][j]);
        }
        if (more) {
            int nb = buf ^ 1;
            As[nb][c40*4+0][row0] = ra0.x; As[nb][c40*4+1][row0] = ra0.y;
            As[nb][c40*4+2][row0] = ra0.z; As[nb][c40*4+3][row0] = ra0.w;
            Bs[nb][c40*4+0][row0] = rb0.x; Bs[nb][c40*4+1][row0] = rb0.y;
            Bs[nb][c40*4+2][row0] = rb0.z; Bs[nb][c40*4+3][row0] = rb0.w;
            As[nb][c41*4+0][row1] = ra1.x; As[nb][c41*4+1][row1] = ra1.y;
            As[nb][c41*4+2][row1] = ra1.z; As[nb][c41*4+3][row1] = ra1.w;
            Bs[nb][c41*4+0][row1] = rb1.x; Bs[nb][c41*4+1][row1] = rb1.y;
            Bs[nb][c41*4+2][row1] = rb1.z; Bs[nb][c41*4+3][row1] = rb1.w;
        }
        __syncthreads();
        buf ^= 1;
    }

    #pragma unroll
    for (int i = 0; i < 4; i++)
        #pragma unroll
        for (int j = 0; j < 4; j++) {
            int m = m0 + ty * 4 + i;
            int n = n0 + tx * 4 + j;
            out[(size_t)m * HH + n] = ex2a((acc[i][j] + bias[n]) * LOG2E2);
        }
}

// ---------------------------------------------------------------------------
// K2: scores. s[q,k] = sum_h We[h] / (Eq[q,h]*Ek[k,h] + 1). Quad-rcp:
//   sum_{i<4} we_i/t_i = [ (we0*t1+we1*t0)*t2t3 + (we2*t3+we3*t2)*t0t1 ]
//                        * rcp(t0*t1*t2*t3)         (t = fma(eq,ek,1) >= 1)
// log-den bounded (~e^24 worst case here) -> no overflow.
// Thread = (q in [0,32), hc in [0,8)); eq[32]+we[32] persistent registers,
// ek streamed from padded smem (LDS.64, conflict-free broadcast).
// ---------------------------------------------------------------------------
#define SQ 32
#define SKT 32
#define KCH 128
#define EK_PITCH 272   // 8*34 floats

__global__ __launch_bounds__(256) void score_kernel(const float* __restrict__ We)
{
    __shared__ float eks[SKT][EK_PITCH];

    int b   = blockIdx.z;
    int q0  = blockIdx.x * SQ;
    int k0  = blockIdx.y * KCH;
    int tid = threadIdx.x;
    int q   = tid >> 3;      // 0..31 (also staging k-row)
    int hc  = tid & 7;       // 0..7  h-chunk of 32

    float eq[32], we[32];
    {
        const float* eqp = g_q + ((size_t)(b * LQ + q0 + q)) * HH + hc * 32;
        const float* wep = We + hc * 32;
        #pragma unroll
        for (int i = 0; i < 8; i++) {
            float4 e4 = *(const float4*)&eqp[i * 4];
            eq[i*4+0] = e4.x; eq[i*4+1] = e4.y; eq[i*4+2] = e4.z; eq[i*4+3] = e4.w;
            float4 w4 = *(const float4*)&wep[i * 4];
            we[i*4+0] = w4.x; we[i*4+1] = w4.y; we[i*4+2] = w4.z; we[i*4+3] = w4.w;
        }
    }

    float* srow = g_s + ((size_t)(b * LQ + q0 + q)) * LK + k0;
    int lane = tid & 31;
    int hbase = hc * 34;

    for (int t = 0; t < KCH / SKT; t++) {
        __syncthreads();
        {
            const float* ekp = g_k + ((size_t)(b * LK + k0 + t * SKT + q)) * HH + hc * 32;
            #pragma unroll
            for (int i = 0; i < 8; i++) {
                float4 e4 = *(const float4*)&ekp[i * 4];
                *(float2*)&eks[q][hbase + i*4]     = make_float2(e4.x, e4.y);
                *(float2*)&eks[q][hbase + i*4 + 2] = make_float2(e4.z, e4.w);
            }
        }
        __syncthreads();

        #pragma unroll 2
        for (int k = 0; k < SKT; k++) {
            float acc0 = 0.0f, acc1 = 0.0f;
            const float* ekr = &eks[k][hbase];
            #pragma unroll
            for (int qd = 0; qd < 8; qd++) {
                float2 ea = *(const float2*)&ekr[4 * qd];
                float2 eb = *(const float2*)&ekr[4 * qd + 2];
                float t0 = fmaf(eq[4*qd+0], ea.x, 1.0f);
                float t1 = fmaf(eq[4*qd+1], ea.y, 1.0f);
                float t2 = fmaf(eq[4*qd+2], eb.x, 1.0f);
                float t3 = fmaf(eq[4*qd+3], eb.y, 1.0f);
                float p01 = t0 * t1;
                float p23 = t2 * t3;
                float n01 = fmaf(we[4*qd+0], t1, we[4*qd+1] * t0);
                float n23 = fmaf(we[4*qd+2], t3, we[4*qd+3] * t2);
                float num = fmaf(n01, p23, n23 * p01);
                float r = rcpa(p01 * p23);
                if (qd & 1) acc1 = fmaf(num, r, acc1);
                else        acc0 = fmaf(num, r, acc0);
            }
            float acc = acc0 + acc1;
            acc += __shfl_xor_sync(0xffffffffu, acc, 1);
            acc += __shfl_xor_sync(0xffffffffu, acc, 2);
            acc += __shfl_xor_sync(0xffffffffu, acc, 4);
            if ((lane & 7) == 0) srow[t * SKT + k] = acc;
        }
    }
}

// ---------------------------------------------------------------------------
// K2b: softmax over k of score = -2*s. Warp per row.
// ---------------------------------------------------------------------------
__global__ __launch_bounds__(256) void softmax_kernel(float* __restrict__ attn)
{
    int row  = blockIdx.x * 8 + (threadIdx.x >> 5);
    int lane = threadIdx.x & 31;
    const float* s = g_s + (size_t)row * LK;

    float vals[16];
    float m = -1e30f;
    #pragma unroll
    for (int i = 0; i < 16; i++) {
        vals[i] = -2.0f * s[lane + 32 * i];
        m = fmaxf(m, vals[i]);
    }
    #pragma unroll
    for (int o = 16; o; o >>= 1) m = fmaxf(m, __shfl_xor_sync(0xffffffffu, m, o));
    float sum = 0.0f;
    #pragma unroll
    for (int i = 0; i < 16; i++) {
        vals[i] = ex2a((vals[i] - m) * 1.4426950408889634f);
        sum += vals[i];
    }
    #pragma unroll
    for (int o = 16; o; o >>= 1) sum += __shfl_xor_sync(0xffffffffu, sum, o);
    float inv = 1.0f / sum;

    float* arow = attn + (size_t)row * LK;
    #pragma unroll
    for (int i = 0; i < 16; i++)
        arow[lane + 32 * i] = vals[i] * inv;
}

// ---------------------------------------------------------------------------
// K3: context partials = attn @ values, split-K2 (deterministic: disjoint
// partial buffers, combined in K3b). Tile 64x64, BK=32, 256 threads, 4x4 reg
// tile, double-buffered smem + register prefetch. Grid 8 x 4 x (B*2).
// ---------------------------------------------------------------------------
__global__ __launch_bounds__(256) void context_kernel(
    const float* __restrict__ values, const float* __restrict__ attn)
{
    __shared__ float As[2][32][68];   // [k][m] transposed
    __shared__ float Vs[2][32][68];   // [k][n]

    int tid = threadIdx.x;
    int b  = blockIdx.z >> 1;
    int ks = blockIdx.z & 1;
    int q0 = blockIdx.x * 64;
    int n0 = blockIdx.y * 64;
    int tx = tid & 15, ty = tid >> 4;
    int kbase = ks * (LK / 2);

    const float* Abase = attn + (size_t)b * LQ * LK + kbase;
    const float* Vbase = values + (size_t)(b * LK + kbase) * HH;

    int arow0 = tid >> 3,         ac40 = tid & 7;
    int arow1 = (tid + 256) >> 3, ac41 = (tid + 256) & 7;
    int vk0 = tid >> 4,           vc40 = tid & 15;
    int vk1 = (tid + 256) >> 4,   vc41 = (tid + 256) & 15;

    float4 ra0, ra1, rv0, rv1;
    ra0 = *(const float4*)&Abase[(size_t)(q0 + arow0) * LK + ac40 * 4];
    ra1 = *(const float4*)&Abase[(size_t)(q0 + arow1) * LK + ac41 * 4];
    rv0 = *(const float4*)&Vbase[(size_t)vk0 * HH + n0 + vc40 * 4];
    rv1 = *(const float4*)&Vbase[(size_t)vk1 * HH + n0 + vc41 * 4];

    As[0][ac40*4+0][arow0] = ra0.x; As[0][ac40*4+1][arow0] = ra0.y;
    As[0][ac40*4+2][arow0] = ra0.z; As[0][ac40*4+3][arow0] = ra0.w;
    As[0][ac41*4+0][arow1] = ra1.x; As[0][ac41*4+1][arow1] = ra1.y;
    As[0][ac41*4+2][arow1] = ra1.z; As[0][ac41*4+3][arow1] = ra1.w;
    *(float4*)&Vs[0][vk0][vc40 * 4] = rv0;
    *(float4*)&Vs[0][vk1][vc41 * 4] = rv1;
    __syncthreads();

    float acc[4][4] = {};
    int buf = 0;

    #pragma unroll 1
    for (int it = 0; it < (LK / 2) / 32; it++) {
        int k1 = (it + 1) * 32;
        bool more = (it + 1 < (LK / 2) / 32);
        if (more) {
            ra0 = *(const float4*)&Abase[(size_t)(q0 + arow0) * LK + k1 + ac40 * 4];
            ra1 = *(const float4*)&Abase[(size_t)(q0 + arow1) * LK + k1 + ac41 * 4];
            rv0 = *(const float4*)&Vbase[(size_t)(k1 + vk0) * HH + n0 + vc40 * 4];
            rv1 = *(const float4*)&Vbase[(size_t)(k1 + vk1) * HH + n0 + vc41 * 4];
        }
        #pragma unroll 8
        for (int kk = 0; kk < 32; kk++) {
            float4 a = *(const float4*)&As[buf][kk][ty * 4];
            float4 v = *(const float4*)&Vs[buf][kk][tx * 4];
            float av[4] = {a.x, a.y, a.z, a.w};
            float vv[4] = {v.x, v.y, v.z, v.w};
            #pragma unroll
            for (int i = 0; i < 4; i++)
                #pragma unroll
                for (int j = 0; j < 4; j++)
                    acc[i][j] = fmaf(av[i], vv[j], acc[i][j]);
        }
        if (more) {
            int nb = buf ^ 1;
            As[nb][ac40*4+0][arow0] = ra0.x; As[nb][ac40*4+1][arow0] = ra0.y;
            As[nb][ac40*4+2][arow0] = ra0.z; As[nb][ac40*4+3][arow0] = ra0.w;
            As[nb][ac41*4+0][arow1] = ra1.x; As[nb][ac41*4+1][arow1] = ra1.y;
            As[nb][ac41*4+2][arow1] = ra1.z; As[nb][ac41*4+3][arow1] = ra1.w;
            *(float4*)&Vs[nb][vk0][vc40 * 4] = rv0;
            *(float4*)&Vs[nb][vk1][vc41 * 4] = rv1;
        }
        __syncthreads();
        buf ^= 1;
    }

    float* part = g_part + (size_t)ks * CTX_ELEMS;
    #pragma unroll
    for (int i = 0; i < 4; i++)
        #pragma unroll
        for (int j = 0; j < 4; j++)
            part[(size_t)(b * LQ + q0 + ty * 4 + i) * HH + n0 + tx * 4 + j] = acc[i][j];
}

// K3b: ctx = part0 + part1
__global__ __launch_bounds__(256) void combine_kernel(float* __restrict__ ctx)
{
    int i = (blockIdx.x * 256 + threadIdx.x) * 4;
    float4 a = *(const float4*)&g_part[i];
    float4 b = *(const float4*)&g_part[CTX_ELEMS + i];
    float4 r = make_float4(a.x + b.x, a.y + b.y, a.z + b.z, a.w + b.w);
    *(float4*)&ctx[i] = r;
}

// ---------------------------------------------------------------------------
// Launch: proj(+exp) -> scores -> softmax -> context(splitK) -> combine.
// Output layout: [context (B*LQ*H) | attention (B*LQ*LK)]. be unused.
// ---------------------------------------------------------------------------
extern "C" void kernel_launch(void* const* d_in, const int* in_sizes, int n_in,
                              void* d_out, int out_size)
{
    const float* query  = (const float*)d_in[0];
    const float* values = (const float*)d_in[1];
    const float* Wq     = (const float*)d_in[2];
    const float* bq     = (const float*)d_in[3];
    const float* Wk     = (const float*)d_in[4];
    const float* bk     = (const float*)d_in[5];
    const float* We     = (const float*)d_in[6];
    // d_in[7] = be, softmax-invariant

    float* out  = (float*)d_out;
    float* ctx  = out;
    float* attn = out + CTX_ELEMS;

    proj_kernel<<<dim3(32, 4, 2), 256>>>(query, values, Wq, bq, Wk, bk);
    score_kernel<<<dim3(LQ / SQ, LK / KCH, BB), 256>>>(We);
    softmax_kernel<<<dim3(BB * LQ / 8), 256>>>(attn);
    context_kernel<<<dim3(8, 4, BB * 2), 256>>>(values, attn);
    combine_kernel<<<dim3(CTX_ELEMS / 1024), 256>>>(ctx);
}

// round 5
// speedup vs baseline: 2.9302x; 1.0357x over previous
#include <cuda_runtime.h>

#define BB 4
#define LQ 512
#define LK 512
#define HH 256

#define CTX_ELEMS (BB*LQ*HH)
#define LOG2E2 2.885390081777927f   // 2*log2(e)

static __device__ float g_q [BB*LQ*HH];     // Eq = exp(2*q_proj), [b][q][h]
static __device__ float g_kT[BB*HH*LK];     // Ek = exp(2*k_proj), TRANSPOSED [b][h][k]
static __device__ float g_s [BB*LQ*LK];     // raw scores; ref score = C - 2s (consts drop)
static __device__ float g_part[2*CTX_ELEMS];// context split-K partials

typedef unsigned long long ull;

__device__ __forceinline__ float ex2a(float x) {
    float e; asm("ex2.approx.ftz.f32 %0, %1;" : "=f"(e) : "f"(x)); return e;
}
__device__ __forceinline__ float rcpa(float x) {
    float r; asm("rcp.approx.ftz.f32 %0, %1;" : "=f"(r) : "f"(x)); return r;
}
// packed f32x2 helpers (Blackwell FFMA2 path — PTX only)
__device__ __forceinline__ ull pk(float x, float y) {
    ull r; asm("mov.b64 %0, {%1, %2};" : "=l"(r) : "f"(x), "f"(y)); return r;
}
__device__ __forceinline__ void upk(ull v, float& x, float& y) {
    asm("mov.b64 {%0, %1}, %2;" : "=f"(x), "=f"(y) : "l"(v));
}
__device__ __forceinline__ ull fma2(ull a, ull b, ull c) {
    ull d; asm("fma.rn.f32x2 %0, %1, %2, %3;" : "=l"(d) : "l"(a), "l"(b), "l"(c)); return d;
}
__device__ __forceinline__ ull mul2(ull a, ull b) {
    ull d; asm("mul.rn.f32x2 %0, %1, %2;" : "=l"(d) : "l"(a), "l"(b)); return d;
}

// ---------------------------------------------------------------------------
// K1: projections + exp epilogue. Double-buffered smem + register prefetch.
// z=0: g_q[b][q][h] = exp(2*(q@WqT+bq));  z=1: g_kT[b][h][k] (transposed!)
// ---------------------------------------------------------------------------
__global__ __launch_bounds__(256) void proj_kernel(
    const float* __restrict__ query, const float* __restrict__ values,
    const float* __restrict__ Wq, const float* __restrict__ bq,
    const float* __restrict__ Wk, const float* __restrict__ bk)
{
    const float* in   = blockIdx.z ? values : query;
    const float* W    = blockIdx.z ? Wk : Wq;
    const float* bias = blockIdx.z ? bk : bq;

    __shared__ float As[2][32][68];
    __shared__ float Bs[2][32][68];

    int tid = threadIdx.x;
    int tx = tid & 15, ty = tid >> 4;
    int m0 = blockIdx.x * 64, n0 = blockIdx.y * 64;

    int row0 = tid >> 3,         c40 = tid & 7;
    int row1 = (tid + 256) >> 3, c41 = (tid + 256) & 7;

    float4 ra0, ra1, rb0, rb1;
    ra0 = *(const float4*)&in[(size_t)(m0 + row0) * HH + c40 * 4];
    rb0 = *(const float4*)&W [(size_t)(n0 + row0) * HH + c40 * 4];
    ra1 = *(const float4*)&in[(size_t)(m0 + row1) * HH + c41 * 4];
    rb1 = *(const float4*)&W [(size_t)(n0 + row1) * HH + c41 * 4];

    As[0][c40*4+0][row0] = ra0.x; As[0][c40*4+1][row0] = ra0.y;
    As[0][c40*4+2][row0] = ra0.z; As[0][c40*4+3][row0] = ra0.w;
    Bs[0][c40*4+0][row0] = rb0.x; Bs[0][c40*4+1][row0] = rb0.y;
    Bs[0][c40*4+2][row0] = rb0.z; Bs[0][c40*4+3][row0] = rb0.w;
    As[0][c41*4+0][row1] = ra1.x; As[0][c41*4+1][row1] = ra1.y;
    As[0][c41*4+2][row1] = ra1.z; As[0][c41*4+3][row1] = ra1.w;
    Bs[0][c41*4+0][row1] = rb1.x; Bs[0][c41*4+1][row1] = rb1.y;
    Bs[0][c41*4+2][row1] = rb1.z; Bs[0][c41*4+3][row1] = rb1.w;
    __syncthreads();

    float acc[4][4] = {};
    int buf = 0;

    #pragma unroll 1
    for (int it = 0; it < HH / 32; it++) {
        int k1 = (it + 1) * 32;
        bool more = (it + 1 < HH / 32);
        if (more) {
            ra0 = *(const float4*)&in[(size_t)(m0 + row0) * HH + k1 + c40 * 4];
            rb0 = *(const float4*)&W [(size_t)(n0 + row0) * HH + k1 + c40 * 4];
            ra1 = *(const float4*)&in[(size_t)(m0 + row1) * HH + k1 + c41 * 4];
            rb1 = *(const float4*)&W [(size_t)(n0 + row1) * HH + k1 + c41 * 4];
        }
        #pragma unroll 8
        for (int kk = 0; kk < 32; kk++) {
            float4 a = *(const float4*)&As[buf][kk][ty * 4];
            float4 b = *(const float4*)&Bs[buf][kk][tx * 4];
            float av[4] = {a.x, a.y, a.z, a.w};
            float bv[4] = {b.x, b.y, b.z, b.w};
            #pragma unroll
            for (int i = 0; i < 4; i++)
                #pragma unroll
                for (int j = 0; j < 4; j++)
                    acc[i][j] = fmaf(av[i], bv[j], acc[i][j]);
        }
        if (more) {
            int nb = buf ^ 1;
            As[nb][c40*4+0][row0] = ra0.x; As[nb][c40*4+1][row0] = ra0.y;
            As[nb][c40*4+2][row0] = ra0.z; As[nb][c40*4+3][row0] = ra0.w;
            Bs[nb][c40*4+0][row0] = rb0.x; Bs[nb][c40*4+1][row0] = rb0.y;
            Bs[nb][c40*4+2][row0] = rb0.z; Bs[nb][c40*4+3][row0] = rb0.w;
            As[nb][c41*4+0][row1] = ra1.x; As[nb][c41*4+1][row1] = ra1.y;
            As[nb][c41*4+2][row1] = ra1.z; As[nb][c41*4+3][row1] = ra1.w;
            Bs[nb][c41*4+0][row1] = rb1.x; Bs[nb][c41*4+1][row1] = rb1.y;
            Bs[nb][c41*4+2][row1] = rb1.z; Bs[nb][c41*4+3][row1] = rb1.w;
        }
        __syncthreads();
        buf ^= 1;
    }

    if (blockIdx.z == 0) {
        #pragma unroll
        for (int i = 0; i < 4; i++)
            #pragma unroll
            for (int j = 0; j < 4; j++) {
                int m = m0 + ty * 4 + i;
                int n = n0 + tx * 4 + j;
                g_q[(size_t)m * HH + n] = ex2a((acc[i][j] + bias[n]) * LOG2E2);
            }
    } else {
        // transposed store: g_kT[b][h][k], h = n, k = m % LK
        int b    = m0 / LK;
        int mloc = (m0 % LK) + ty * 4;
        #pragma unroll
        for (int j = 0; j < 4; j++) {
            int n = n0 + tx * 4 + j;
            float4 v;
            v.x = ex2a((acc[0][j] + bias[n]) * LOG2E2);
            v.y = ex2a((acc[1][j] + bias[n]) * LOG2E2);
            v.z = ex2a((acc[2][j] + bias[n]) * LOG2E2);
            v.w = ex2a((acc[3][j] + bias[n]) * LOG2E2);
            *(float4*)&g_kT[((size_t)b * HH + n) * LK + mloc] = v;
        }
    }
}

// ---------------------------------------------------------------------------
// K2: scores via packed f32x2, quad-rcp over h, packed over k (2 k/lane).
//   s[q,k] = sum_h We[h]/(Eq[q,h]*Ek[k,h]+1);  t = fma(eq,ek,1) >= 1
//   quad: sum we_i/t_i = [n01*d23 + n23*d01] * rcp(d01*d23)   (all packed)
// Thread = (qrow 0..15, hc 0..15); owns h = hc + 16j, j=0..15.
// Block tile: 32 q (2 passes) x 64 k (2 staged subtiles of 32 k).
// eks pitch 34: float2-aligned (136B % 8 == 0), LDS.64 banks 2hc..2hc+1
// distinct across 16 hc -> conflict-free, broadcast across 2 q-lanes.
// ---------------------------------------------------------------------------
__global__ __launch_bounds__(256) void score_kernel(const float* __restrict__ We)
{
    __shared__ float eks[256][34];   // 34 KB

    int b   = blockIdx.z;
    int q0  = blockIdx.x * 32;
    int k0  = blockIdx.y * 64;
    int tid = threadIdx.x;
    int qrow = tid >> 4;     // 0..15
    int hc   = tid & 15;     // 0..15

    const ull ONE2 = pk(1.0f, 1.0f);

    ull wep[16];
    #pragma unroll
    for (int j = 0; j < 16; j++) {
        float w = We[hc + 16 * j];
        wep[j] = pk(w, w);
    }

    #pragma unroll 1
    for (int st = 0; st < 2; st++) {
        int kb = k0 + st * 32;
        __syncthreads();
        // stage: thread t copies h=t row, 32 k floats (float2 stores for align)
        {
            const float* src = g_kT + ((size_t)(b * HH) + tid) * LK + kb;
            #pragma unroll
            for (int c = 0; c < 8; c++) {
                float4 v = *(const float4*)&src[c * 4];
                *(float2*)&eks[tid][c * 4]     = make_float2(v.x, v.y);
                *(float2*)&eks[tid][c * 4 + 2] = make_float2(v.z, v.w);
            }
        }
        __syncthreads();

        #pragma unroll 1
        for (int qp = 0; qp < 2; qp++) {
            int q = q0 + qp * 16 + qrow;
            ull eqp[16];
            {
                const float* eqb = g_q + ((size_t)(b * LQ) + q) * HH;
                #pragma unroll
                for (int j = 0; j < 16; j++) {
                    float e = eqb[hc + 16 * j];
                    eqp[j] = pk(e, e);
                }
            }
            float* srow = g_s + ((size_t)(b * LQ) + q) * LK + kb;

            #pragma unroll 4
            for (int kp = 0; kp < 16; kp++) {
                ull acc = pk(0.0f, 0.0f);
                #pragma unroll
                for (int jq = 0; jq < 4; jq++) {
                    float2 f0 = *(const float2*)&eks[hc + 16*(4*jq+0)][2*kp];
                    float2 f1 = *(const float2*)&eks[hc + 16*(4*jq+1)][2*kp];
                    float2 f2 = *(const float2*)&eks[hc + 16*(4*jq+2)][2*kp];
                    float2 f3 = *(const float2*)&eks[hc + 16*(4*jq+3)][2*kp];
                    ull t0 = fma2(pk(f0.x, f0.y), eqp[4*jq+0], ONE2);
                    ull t1 = fma2(pk(f1.x, f1.y), eqp[4*jq+1], ONE2);
                    ull t2 = fma2(pk(f2.x, f2.y), eqp[4*jq+2], ONE2);
                    ull t3 = fma2(pk(f3.x, f3.y), eqp[4*jq+3], ONE2);
                    ull d01 = mul2(t0, t1);
                    ull d23 = mul2(t2, t3);
                    ull n01 = fma2(wep[4*jq+0], t1, mul2(wep[4*jq+1], t0));
                    ull n23 = fma2(wep[4*jq+2], t3, mul2(wep[4*jq+3], t2));
                    ull nQ  = fma2(n01, d23, mul2(n23, d01));
                    ull dQ  = mul2(d01, d23);
                    float da, db; upk(dQ, da, db);
                    ull rp = pk(rcpa(da), rcpa(db));
                    acc = fma2(nQ, rp, acc);
                }
                float a0, a1; upk(acc, a0, a1);
                a0 += __shfl_xor_sync(0xffffffffu, a0, 1);
                a1 += __shfl_xor_sync(0xffffffffu, a1, 1);
                a0 += __shfl_xor_sync(0xffffffffu, a0, 2);
                a1 += __shfl_xor_sync(0xffffffffu, a1, 2);
                a0 += __shfl_xor_sync(0xffffffffu, a0, 4);
                a1 += __shfl_xor_sync(0xffffffffu, a1, 4);
                a0 += __shfl_xor_sync(0xffffffffu, a0, 8);
                a1 += __shfl_xor_sync(0xffffffffu, a1, 8);
                if (hc == 0)
                    *(float2*)&srow[2 * kp] = make_float2(a0, a1);
            }
        }
    }
}

// ---------------------------------------------------------------------------
// K2b: softmax over k of score = -2*s. Warp per row.
// ---------------------------------------------------------------------------
__global__ __launch_bounds__(256) void softmax_kernel(float* __restrict__ attn)
{
    int row  = blockIdx.x * 8 + (threadIdx.x >> 5);
    int lane = threadIdx.x & 31;
    const float* s = g_s + (size_t)row * LK;

    float vals[16];
    float m = -1e30f;
    #pragma unroll
    for (int i = 0; i < 16; i++) {
        vals[i] = -2.0f * s[lane + 32 * i];
        m = fmaxf(m, vals[i]);
    }
    #pragma unroll
    for (int o = 16; o; o >>= 1) m = fmaxf(m, __shfl_xor_sync(0xffffffffu, m, o));
    float sum = 0.0f;
    #pragma unroll
    for (int i = 0; i < 16; i++) {
        vals[i] = ex2a((vals[i] - m) * 1.4426950408889634f);
        sum += vals[i];
    }
    #pragma unroll
    for (int o = 16; o; o >>= 1) sum += __shfl_xor_sync(0xffffffffu, sum, o);
    float inv = 1.0f / sum;

    float* arow = attn + (size_t)row * LK;
    #pragma unroll
    for (int i = 0; i < 16; i++)
        arow[lane + 32 * i] = vals[i] * inv;
}

// ---------------------------------------------------------------------------
// K3: context partials = attn @ values, split-K2, double-buffered.
// ---------------------------------------------------------------------------
__global__ __launch_bounds__(256) void context_kernel(
    const float* __restrict__ values, const float* __restrict__ attn)
{
    __shared__ float As[2][32][68];
    __shared__ float Vs[2][32][68];

    int tid = threadIdx.x;
    int b  = blockIdx.z >> 1;
    int ks = blockIdx.z & 1;
    int q0 = blockIdx.x * 64;
    int n0 = blockIdx.y * 64;
    int tx = tid & 15, ty = tid >> 4;
    int kbase = ks * (LK / 2);

    const float* Abase = attn + (size_t)b * LQ * LK + kbase;
    const float* Vbase = values + (size_t)(b * LK + kbase) * HH;

    int arow0 = tid >> 3,         ac40 = tid & 7;
    int arow1 = (tid + 256) >> 3, ac41 = (tid + 256) & 7;
    int vk0 = tid >> 4,           vc40 = tid & 15;
    int vk1 = (tid + 256) >> 4,   vc41 = (tid + 256) & 15;

    float4 ra0, ra1, rv0, rv1;
    ra0 = *(const float4*)&Abase[(size_t)(q0 + arow0) * LK + ac40 * 4];
    ra1 = *(const float4*)&Abase[(size_t)(q0 + arow1) * LK + ac41 * 4];
    rv0 = *(const float4*)&Vbase[(size_t)vk0 * HH + n0 + vc40 * 4];
    rv1 = *(const float4*)&Vbase[(size_t)vk1 * HH + n0 + vc41 * 4];

    As[0][ac40*4+0][arow0] = ra0.x; As[0][ac40*4+1][arow0] = ra0.y;
    As[0][ac40*4+2][arow0] = ra0.z; As[0][ac40*4+3][arow0] = ra0.w;
    As[0][ac41*4+0][arow1] = ra1.x; As[0][ac41*4+1][arow1] = ra1.y;
    As[0][ac41*4+2][arow1] = ra1.z; As[0][ac41*4+3][arow1] = ra1.w;
    *(float4*)&Vs[0][vk0][vc40 * 4] = rv0;
    *(float4*)&Vs[0][vk1][vc41 * 4] = rv1;
    __syncthreads();

    float acc[4][4] = {};
    int buf = 0;

    #pragma unroll 1
    for (int it = 0; it < (LK / 2) / 32; it++) {
        int k1 = (it + 1) * 32;
        bool more = (it + 1 < (LK / 2) / 32);
        if (more) {
            ra0 = *(const float4*)&Abase[(size_t)(q0 + arow0) * LK + k1 + ac40 * 4];
            ra1 = *(const float4*)&Abase[(size_t)(q0 + arow1) * LK + k1 + ac41 * 4];
            rv0 = *(const float4*)&Vbase[(size_t)(k1 + vk0) * HH + n0 + vc40 * 4];
            rv1 = *(const float4*)&Vbase[(size_t)(k1 + vk1) * HH + n0 + vc41 * 4];
        }
        #pragma unroll 8
        for (int kk = 0; kk < 32; kk++) {
            float4 a = *(const float4*)&As[buf][kk][ty * 4];
            float4 v = *(const float4*)&Vs[buf][kk][tx * 4];
            float av[4] = {a.x, a.y, a.z, a.w};
            float vv[4] = {v.x, v.y, v.z, v.w};
            #pragma unroll
            for (int i = 0; i < 4; i++)
                #pragma unroll
                for (int j = 0; j < 4; j++)
                    acc[i][j] = fmaf(av[i], vv[j], acc[i][j]);
        }
        if (more) {
            int nb = buf ^ 1;
            As[nb][ac40*4+0][arow0] = ra0.x; As[nb][ac40*4+1][arow0] = ra0.y;
            As[nb][ac40*4+2][arow0] = ra0.z; As[nb][ac40*4+3][arow0] = ra0.w;
            As[nb][ac41*4+0][arow1] = ra1.x; As[nb][ac41*4+1][arow1] = ra1.y;
            As[nb][ac41*4+2][arow1] = ra1.z; As[nb][ac41*4+3][arow1] = ra1.w;
            *(float4*)&Vs[nb][vk0][vc40 * 4] = rv0;
            *(float4*)&Vs[nb][vk1][vc41 * 4] = rv1;
        }
        __syncthreads();
        buf ^= 1;
    }

    float* part = g_part + (size_t)ks * CTX_ELEMS;
    #pragma unroll
    for (int i = 0; i < 4; i++)
        #pragma unroll
        for (int j = 0; j < 4; j++)
            part[(size_t)(b * LQ + q0 + ty * 4 + i) * HH + n0 + tx * 4 + j] = acc[i][j];
}

// K3b: ctx = part0 + part1
__global__ __launch_bounds__(256) void combine_kernel(float* __restrict__ ctx)
{
    int i = (blockIdx.x * 256 + threadIdx.x) * 4;
    float4 a = *(const float4*)&g_part[i];
    float4 b = *(const float4*)&g_part[CTX_ELEMS + i];
    *(float4*)&ctx[i] = make_float4(a.x + b.x, a.y + b.y, a.z + b.z, a.w + b.w);
}

// ---------------------------------------------------------------------------
// Launch: proj(+exp, K transposed) -> scores(f32x2) -> softmax -> context -> combine.
// Output layout: [context (B*LQ*H) | attention (B*LQ*LK)]. be unused.
// ---------------------------------------------------------------------------
extern "C" void kernel_launch(void* const* d_in, const int* in_sizes, int n_in,
                              void* d_out, int out_size)
{
    const float* query  = (const float*)d_in[0];
    const float* values = (const float*)d_in[1];
    const float* Wq     = (const float*)d_in[2];
    const float* bq     = (const float*)d_in[3];
    const float* Wk     = (const float*)d_in[4];
    const float* bk     = (const float*)d_in[5];
    const float* We     = (const float*)d_in[6];
    // d_in[7] = be, softmax-invariant

    float* out  = (float*)d_out;
    float* ctx  = out;
    float* attn = out + CTX_ELEMS;

    proj_kernel<<<dim3(32, 4, 2), 256>>>(query, values, Wq, bq, Wk, bk);
    score_kernel<<<dim3(LQ / 32, LK / 64, BB), 256>>>(We);
    softmax_kernel<<<dim3(BB * LQ / 8), 256>>>(attn);
    context_kernel<<<dim3(8, 4, BB * 2), 256>>>(values, attn);
    combine_kernel<<<dim3(CTX_ELEMS / 1024), 256>>>(ctx);
}